// round 1
// baseline (speedup 1.0000x reference)
#include <cuda_runtime.h>
#include <cstdint>

#define B_DIM 8192
#define F_DIM 64
#define NXX   82
#define NYY   67
#define P_DIM (NXX * NYY)   // 5494
#define NPAD  5504          // 86 * 64

#define BM 128
#define BN 64
#define GEMM_THREADS 256

// Scratch: permuted (transpose-folded) W in tf32 bits, permuted bias.
__device__ float g_Wp[NPAD * F_DIM];
__device__ float g_bp[NPAD];

__device__ __forceinline__ uint32_t f2tf32(float x) {
    uint32_t r;
    asm("cvt.rna.tf32.f32 %0, %1;" : "=r"(r) : "f"(x));
    return r;
}

// Fold the output transpose into W: W'[q][f] = W[p][f], q = x*67+y, p = y*82+x.
// Also rounds W to tf32 so the MMA sees correctly-rounded operands.
__global__ void permute_kernel(const float* __restrict__ W,
                               const float* __restrict__ bias) {
    int idx = blockIdx.x * blockDim.x + threadIdx.x;
    if (idx >= NPAD * F_DIM) return;
    int q = idx >> 6;
    int f = idx & 63;
    float v = 0.0f;
    if (q < P_DIM) {
        int x = q / NYY;
        int y = q - x * NYY;
        int p = y * NXX + x;
        v = W[p * F_DIM + f];
    }
    g_Wp[idx] = __uint_as_float(f2tf32(v));
    if (f == 0) {
        float bb = 0.0f;
        if (q < P_DIM) {
            int x = q / NYY;
            int y = q - x * NYY;
            bb = bias[y * NXX + x];
        }
        g_bp[q] = bb;
    }
}

// C[b][q] = sum_f A[b][f] * W'[q][f] + bias'[q]; out is [B, 5494] contiguous.
// Tiles: BM=128 x BN=64, K=64 single pass. 8 warps: 4 (m) x 2 (n),
// warp tile 32x32 = 2 m-frags x 4 n-frags of m16n8k8 tf32.
__global__ __launch_bounds__(GEMM_THREADS, 3)
void gemm_kernel(const float* __restrict__ A, float* __restrict__ out) {
    // 48 KB exactly; XOR swizzle (col4 ^= row&7) keeps frag reads conflict-free.
    __shared__ uint32_t Asm[BM * 64];
    __shared__ uint32_t Bsm[BN * 64];

    const int tid = threadIdx.x;
    const int bn0 = blockIdx.x * BN;   // n fast -> concurrent blocks share A in L2
    const int bm0 = blockIdx.y * BM;

    {
        const int c4 = tid & 15;   // float4 column
        const int r0 = tid >> 4;   // 16 rows per pass
        const float4* Ag = (const float4*)(A + (size_t)bm0 * 64);
        #pragma unroll
        for (int i = 0; i < 8; i++) {
            int r = r0 + i * 16;
            float4 v = Ag[r * 16 + c4];
            int pc4 = c4 ^ (r & 7);
            uint4 t;
            t.x = f2tf32(v.x); t.y = f2tf32(v.y);
            t.z = f2tf32(v.z); t.w = f2tf32(v.w);
            *(uint4*)&Asm[r * 64 + pc4 * 4] = t;
        }
        const float4* Bg = (const float4*)(g_Wp + (size_t)bn0 * 64);
        #pragma unroll
        for (int i = 0; i < 4; i++) {
            int r = r0 + i * 16;
            float4 v = Bg[r * 16 + c4];
            int pc4 = c4 ^ (r & 7);
            *(float4*)&Bsm[r * 64 + pc4 * 4] = v;   // already tf32-rounded
        }
    }
    __syncthreads();

    const int warp = tid >> 5;
    const int lane = tid & 31;
    const int wm = (warp & 3) * 32;
    const int wn = (warp >> 2) * 32;
    const int lrow = lane >> 2;   // groupID
    const int lcol = lane & 3;    // threadID_in_group

    float acc[2][4][4];
    #pragma unroll
    for (int i = 0; i < 2; i++)
        #pragma unroll
        for (int j = 0; j < 4; j++)
            #pragma unroll
            for (int k = 0; k < 4; k++) acc[i][j][k] = 0.0f;

    #pragma unroll
    for (int ks = 0; ks < 8; ks++) {
        const int c0 = ks * 2;          // col4 index of low half of k-block
        uint32_t a[2][4];
        #pragma unroll
        for (int mf = 0; mf < 2; mf++) {
            int ra = wm + mf * 16 + lrow;   // ra&7 == lrow
            int rb = ra + 8;
            a[mf][0] = Asm[ra * 64 + ((c0       ^ lrow) << 2) + lcol];
            a[mf][1] = Asm[rb * 64 + ((c0       ^ lrow) << 2) + lcol];
            a[mf][2] = Asm[ra * 64 + (((c0 + 1) ^ lrow) << 2) + lcol];
            a[mf][3] = Asm[rb * 64 + (((c0 + 1) ^ lrow) << 2) + lcol];
        }
        #pragma unroll
        for (int nf = 0; nf < 4; nf++) {
            int rn = wn + nf * 8 + lrow;    // rn&7 == lrow
            uint32_t b0 = Bsm[rn * 64 + ((c0       ^ lrow) << 2) + lcol];
            uint32_t b1 = Bsm[rn * 64 + (((c0 + 1) ^ lrow) << 2) + lcol];
            #pragma unroll
            for (int mf = 0; mf < 2; mf++) {
                asm volatile(
                    "mma.sync.aligned.m16n8k8.row.col.f32.tf32.tf32.f32 "
                    "{%0,%1,%2,%3}, {%4,%5,%6,%7}, {%8,%9}, {%0,%1,%2,%3};\n"
                    : "+f"(acc[mf][nf][0]), "+f"(acc[mf][nf][1]),
                      "+f"(acc[mf][nf][2]), "+f"(acc[mf][nf][3])
                    : "r"(a[mf][0]), "r"(a[mf][1]), "r"(a[mf][2]), "r"(a[mf][3]),
                      "r"(b0), "r"(b1));
            }
        }
    }

    // Store with bias. q is the contiguous output column -> coalesced 32B sectors.
    const int q0 = bn0 + wn + 2 * lcol;
    #pragma unroll
    for (int mf = 0; mf < 2; mf++) {
        int grow = bm0 + wm + mf * 16 + lrow;
        #pragma unroll
        for (int nf = 0; nf < 4; nf++) {
            int q = q0 + nf * 8;
            if (q < P_DIM) {
                float bq0 = g_bp[q];
                float bq1 = g_bp[q + 1];
                float2 v0 = make_float2(acc[mf][nf][0] + bq0, acc[mf][nf][1] + bq1);
                float2 v1 = make_float2(acc[mf][nf][2] + bq0, acc[mf][nf][3] + bq1);
                *(float2*)&out[(size_t)grow * P_DIM + q] = v0;
                *(float2*)&out[(size_t)(grow + 8) * P_DIM + q] = v1;
            }
        }
    }
}

extern "C" void kernel_launch(void* const* d_in, const int* in_sizes, int n_in,
                              void* d_out, int out_size) {
    const float* inputs = (const float*)d_in[0];   // [8192, 64]
    const float* W      = (const float*)d_in[1];   // [5494, 64]
    const float* bias   = (const float*)d_in[2];   // [5494]
    float* out = (float*)d_out;                    // [8192, 82, 67, 1]

    (void)in_sizes; (void)n_in; (void)out_size;

    int pthreads = 256;
    int pblocks = (NPAD * F_DIM + pthreads - 1) / pthreads;
    permute_kernel<<<pblocks, pthreads>>>(W, bias);

    dim3 grid(NPAD / BN, B_DIM / BM);   // (86, 64)
    gemm_kernel<<<grid, GEMM_THREADS>>>(inputs, out);
}